// round 1
// baseline (speedup 1.0000x reference)
#include <cuda_runtime.h>
#include <math.h>

#define D 1024
#define LSEQ 2048
#define BATCH 2
#define NH 16
#define HDIM 64
#define NROWS 4096  // BATCH*LSEQ

// Scratch (allocation-free rule: __device__ globals)
__device__ float g_q[(size_t)NROWS * D];
__device__ float g_k[(size_t)NROWS * D];
__device__ float g_v[(size_t)NROWS * D];
__device__ float g_ctx[(size_t)NROWS * D];

// ---------------------------------------------------------------------------
// 128x128 fp32 GEMM: C[M=4096, N=1024] = A[4096,1024] @ W[1024,1024] + bias
// 256 threads, 8x8 thread tile, BK=16.
// SCATTER=true: write to (B,H,L,hd) layout for attention.
// ---------------------------------------------------------------------------
template <bool SCATTER>
__device__ __forceinline__ void gemm_body(const float* __restrict__ A,
                                          const float* __restrict__ W,
                                          const float* __restrict__ bias,
                                          float* __restrict__ C) {
    __shared__ float As[16 * 132];  // transposed A tile, padded width 132
    __shared__ float Bs[16 * 128];

    const int tid = threadIdx.x;
    const int bm = blockIdx.y * 128;
    const int bn = blockIdx.x * 128;

    const int warp = tid >> 5, lane = tid & 31;
    const int wy = warp & 3, wx = warp >> 2;   // 4 x 2 warp grid
    const int ty = lane >> 3, tx = lane & 7;   // 4 x 8 thread grid
    const int row0 = wy * 32 + ty * 8;
    const int col0 = wx * 64 + tx * 8;

    float c[8][8];
#pragma unroll
    for (int i = 0; i < 8; i++)
#pragma unroll
        for (int j = 0; j < 8; j++) c[i][j] = 0.0f;

    for (int k0 = 0; k0 < D; k0 += 16) {
        // Load A tile 128x16, store transposed As[k][m]
#pragma unroll
        for (int it = 0; it < 2; it++) {
            int idx = tid + it * 256;
            int r = idx >> 2, c4 = idx & 3;
            float4 va = *(const float4*)(A + (size_t)(bm + r) * D + k0 + c4 * 4);
            As[(c4 * 4 + 0) * 132 + r] = va.x;
            As[(c4 * 4 + 1) * 132 + r] = va.y;
            As[(c4 * 4 + 2) * 132 + r] = va.z;
            As[(c4 * 4 + 3) * 132 + r] = va.w;
        }
        // Load B tile 16x128 native
#pragma unroll
        for (int it = 0; it < 2; it++) {
            int idx = tid + it * 256;
            int r = idx >> 5, c4 = idx & 31;
            *(float4*)(Bs + r * 128 + c4 * 4) =
                *(const float4*)(W + (size_t)(k0 + r) * D + bn + c4 * 4);
        }
        __syncthreads();

#pragma unroll
        for (int k = 0; k < 16; k++) {
            float a[8], b[8];
            *(float4*)(a + 0) = *(float4*)(As + k * 132 + row0);
            *(float4*)(a + 4) = *(float4*)(As + k * 132 + row0 + 4);
            *(float4*)(b + 0) = *(float4*)(Bs + k * 128 + col0);
            *(float4*)(b + 4) = *(float4*)(Bs + k * 128 + col0 + 4);
#pragma unroll
            for (int i = 0; i < 8; i++)
#pragma unroll
                for (int j = 0; j < 8; j++) c[i][j] += a[i] * b[j];
        }
        __syncthreads();
    }

    // Epilogue: bias + store
#pragma unroll
    for (int i = 0; i < 8; i++) {
        int m = bm + row0 + i;
#pragma unroll
        for (int jv = 0; jv < 2; jv++) {
            int n = bn + col0 + jv * 4;
            float4 v;
            v.x = c[i][jv * 4 + 0] + bias[n + 0];
            v.y = c[i][jv * 4 + 1] + bias[n + 1];
            v.z = c[i][jv * 4 + 2] + bias[n + 2];
            v.w = c[i][jv * 4 + 3] + bias[n + 3];
            if (SCATTER) {
                int b_ = m >> 11, l = m & 2047;
                int hh = n >> 6, d = n & 63;
                *(float4*)(C + ((size_t)((b_ * NH + hh) * LSEQ + l)) * HDIM + d) = v;
            } else {
                *(float4*)(C + (size_t)m * D + n) = v;
            }
        }
    }
}

__global__ void __launch_bounds__(256) qkv_kernel(
    const float* __restrict__ x,
    const float* __restrict__ Wq, const float* __restrict__ bq,
    const float* __restrict__ Wk, const float* __restrict__ bk,
    const float* __restrict__ Wv, const float* __restrict__ bv) {
    const float *W, *bias;
    float* out;
    if (blockIdx.z == 0) { W = Wq; bias = bq; out = g_q; }
    else if (blockIdx.z == 1) { W = Wk; bias = bk; out = g_k; }
    else { W = Wv; bias = bv; out = g_v; }
    gemm_body<true>(x, W, bias, out);
}

__global__ void __launch_bounds__(256) oproj_kernel(
    const float* __restrict__ Wo, const float* __restrict__ bo,
    float* __restrict__ out) {
    gemm_body<false>(g_ctx, Wo, bo, out);
}

// ---------------------------------------------------------------------------
// Flash attention (softmax-one, causal). BQ=128, BK=64, hd=64, 128 threads.
// S = Q K^T via 8x8 register tiles (Q^T, K^T in swizzled smem).
// Softmax kept in registers; P broadcast via shfl for the PV GEMM (no P smem).
// ---------------------------------------------------------------------------
__global__ void __launch_bounds__(128) attn_kernel(const float* __restrict__ Qg,
                                                   const float* __restrict__ Kg,
                                                   const float* __restrict__ Vg,
                                                   float* __restrict__ ctx) {
    extern __shared__ float sm[];
    float* Qt = sm;               // [64][128] d-major, swizzled
    float* Kt = sm + 64 * 128;    // [64][64]  d-major, swizzled
    float* Vs = sm + 64 * 128 + 64 * 64;  // [64][64] native

    const int bh = blockIdx.y;                      // b*NH + h
    const int qt = (gridDim.x - 1) - blockIdx.x;    // heavy tiles first
    const int q0 = qt * 128;
    const float* Qb = Qg + (size_t)bh * LSEQ * HDIM;
    const float* Kb = Kg + (size_t)bh * LSEQ * HDIM;
    const float* Vb = Vg + (size_t)bh * LSEQ * HDIM;

    const int tid = threadIdx.x;
    const int warp = tid >> 5, lane = tid & 31;
    const int rg = lane >> 3, cg = lane & 7;
    const int rowbase = warp * 32 + rg * 8;  // local q row of this thread's tile

    // Load Q tile (128 x 64) transposed into Qt[d][r] with XOR swizzle
#pragma unroll
    for (int it = 0; it < 16; it++) {
        int idx = tid + it * 128;
        int r = idx >> 4, c4 = idx & 15;
        float4 v = *(const float4*)(Qb + (size_t)(q0 + r) * HDIM + c4 * 4);
        int sr = (((r >> 2) ^ (c4 & 7)) << 2) + (r & 3);
        Qt[(c4 * 4 + 0) * 128 + sr] = v.x;
        Qt[(c4 * 4 + 1) * 128 + sr] = v.y;
        Qt[(c4 * 4 + 2) * 128 + sr] = v.z;
        Qt[(c4 * 4 + 3) * 128 + sr] = v.w;
    }

    float acc[8][8];
    float m_i[8], l_i[8];
    const float NEG_INF = __int_as_float(0xff800000);
#pragma unroll
    for (int i = 0; i < 8; i++) {
        m_i[i] = NEG_INF;
        l_i[i] = 0.0f;
#pragma unroll
        for (int j = 0; j < 8; j++) acc[i][j] = 0.0f;
    }
    __syncthreads();

    const int nkt = 2 * qt + 2;
    for (int kt = 0; kt < nkt; kt++) {
        const int k0 = kt * 64;
        // Load K (transposed+swizzled) and V (native)
#pragma unroll
        for (int it = 0; it < 8; it++) {
            int idx = tid + it * 128;
            int j = idx >> 4, c4 = idx & 15;
            float4 kv = *(const float4*)(Kb + (size_t)(k0 + j) * HDIM + c4 * 4);
            int sj = (((j >> 2) ^ (c4 & 7)) << 2) + (j & 3);
            Kt[(c4 * 4 + 0) * 64 + sj] = kv.x;
            Kt[(c4 * 4 + 1) * 64 + sj] = kv.y;
            Kt[(c4 * 4 + 2) * 64 + sj] = kv.z;
            Kt[(c4 * 4 + 3) * 64 + sj] = kv.w;
            float4 vv = *(const float4*)(Vb + (size_t)(k0 + j) * HDIM + c4 * 4);
            *(float4*)(Vs + j * 64 + c4 * 4) = vv;
        }
        __syncthreads();

        // S = Q K^T  (M=128, N=64, K=64), 8x8 per thread
        float s[8][8];
#pragma unroll
        for (int i = 0; i < 8; i++)
#pragma unroll
            for (int j = 0; j < 8; j++) s[i][j] = 0.0f;

#pragma unroll 8
        for (int d = 0; d < 64; d++) {
            int sw = (d >> 2) & 7;
            float a[8], b[8];
            *(float4*)(a + 0) = *(float4*)(Qt + d * 128 + (((warp * 8 + rg * 2 + 0) ^ sw) << 2));
            *(float4*)(a + 4) = *(float4*)(Qt + d * 128 + (((warp * 8 + rg * 2 + 1) ^ sw) << 2));
            *(float4*)(b + 0) = *(float4*)(Kt + d * 64 + (((cg * 2 + 0) ^ sw) << 2));
            *(float4*)(b + 4) = *(float4*)(Kt + d * 64 + (((cg * 2 + 1) ^ sw) << 2));
#pragma unroll
            for (int i = 0; i < 8; i++)
#pragma unroll
                for (int j = 0; j < 8; j++) s[i][j] += a[i] * b[j];
        }

        // Scale + causal mask (only the two diagonal-straddling tiles need it)
        const float scale = 0.125f;  // 1/sqrt(64)
        if (kt >= 2 * qt) {
#pragma unroll
            for (int i = 0; i < 8; i++) {
                int qrow = q0 + rowbase + i;
#pragma unroll
                for (int j = 0; j < 8; j++) {
                    int kcol = k0 + cg * 8 + j;
                    s[i][j] = (kcol <= qrow) ? s[i][j] * scale : NEG_INF;
                }
            }
        } else {
#pragma unroll
            for (int i = 0; i < 8; i++)
#pragma unroll
                for (int j = 0; j < 8; j++) s[i][j] *= scale;
        }

        // Online softmax (rows owned by 8 cg-lanes of same warp)
#pragma unroll
        for (int i = 0; i < 8; i++) {
            float mx = s[i][0];
#pragma unroll
            for (int j = 1; j < 8; j++) mx = fmaxf(mx, s[i][j]);
            mx = fmaxf(mx, __shfl_xor_sync(0xffffffffu, mx, 1));
            mx = fmaxf(mx, __shfl_xor_sync(0xffffffffu, mx, 2));
            mx = fmaxf(mx, __shfl_xor_sync(0xffffffffu, mx, 4));
            float mnew = fmaxf(m_i[i], mx);
            float corr = __expf(m_i[i] - mnew);
            m_i[i] = mnew;
            float rs = 0.0f;
#pragma unroll
            for (int j = 0; j < 8; j++) {
                s[i][j] = __expf(s[i][j] - mnew);
                rs += s[i][j];
            }
            rs += __shfl_xor_sync(0xffffffffu, rs, 1);
            rs += __shfl_xor_sync(0xffffffffu, rs, 2);
            rs += __shfl_xor_sync(0xffffffffu, rs, 4);
            l_i[i] = l_i[i] * corr + rs;
#pragma unroll
            for (int dd = 0; dd < 8; dd++) acc[i][dd] *= corr;
        }

        // PV: acc[r][d] += P[r][j] * V[j][d]; P fragments broadcast via shfl
#pragma unroll 1
        for (int jt = 0; jt < 8; jt++) {
            int src = (lane & 24) | jt;
#pragma unroll
            for (int jj = 0; jj < 8; jj++) {
                int j = jt * 8 + jj;
                float4 b0 = *(float4*)(Vs + j * 64 + cg * 8);
                float4 b1 = *(float4*)(Vs + j * 64 + cg * 8 + 4);
#pragma unroll
                for (int i = 0; i < 8; i++) {
                    float a = __shfl_sync(0xffffffffu, s[i][jj], src);
                    acc[i][0] += a * b0.x;
                    acc[i][1] += a * b0.y;
                    acc[i][2] += a * b0.z;
                    acc[i][3] += a * b0.w;
                    acc[i][4] += a * b1.x;
                    acc[i][5] += a * b1.y;
                    acc[i][6] += a * b1.z;
                    acc[i][7] += a * b1.w;
                }
            }
        }
        __syncthreads();  // Kt/Vs consumed before next tile overwrites
    }

    // Write context in (B, L, D) row-major layout for the output projection
    const int b_ = bh >> 4, hh = bh & 15;
#pragma unroll
    for (int i = 0; i < 8; i++) {
        float inv = 1.0f / (1.0f + l_i[i]);  // softmax-one denominator
        int gr = q0 + rowbase + i;
        float* dst = g_ctx + ((size_t)(b_ * LSEQ + gr)) * D + hh * 64 + cg * 8;
        float4 o0, o1;
        o0.x = acc[i][0] * inv; o0.y = acc[i][1] * inv;
        o0.z = acc[i][2] * inv; o0.w = acc[i][3] * inv;
        o1.x = acc[i][4] * inv; o1.y = acc[i][5] * inv;
        o1.z = acc[i][6] * inv; o1.w = acc[i][7] * inv;
        *(float4*)dst = o0;
        *(float4*)(dst + 4) = o1;
    }
    (void)ctx;
}

// ---------------------------------------------------------------------------
extern "C" void kernel_launch(void* const* d_in, const int* in_sizes, int n_in,
                              void* d_out, int out_size) {
    (void)in_sizes; (void)n_in; (void)out_size;
    const float* x  = (const float*)d_in[0];
    const float* Wq = (const float*)d_in[1];
    const float* bq = (const float*)d_in[2];
    const float* Wk = (const float*)d_in[3];
    const float* bk = (const float*)d_in[4];
    const float* Wv = (const float*)d_in[5];
    const float* bv = (const float*)d_in[6];
    const float* Wo = (const float*)d_in[7];
    const float* bo = (const float*)d_in[8];

    float* qp;
    float* kp;
    float* vp;
    cudaGetSymbolAddress((void**)&qp, g_q);
    cudaGetSymbolAddress((void**)&kp, g_k);
    cudaGetSymbolAddress((void**)&vp, g_v);

    // QKV projections: grid (N/128, M/128, 3)
    qkv_kernel<<<dim3(8, 32, 3), 256>>>(x, Wq, bq, Wk, bk, Wv, bv);

    // Flash attention: 64KB dynamic smem
    cudaFuncSetAttribute(attn_kernel, cudaFuncAttributeMaxDynamicSharedMemorySize,
                         65536);
    attn_kernel<<<dim3(16, 32), 128, 65536>>>(qp, kp, vp, nullptr);

    // Output projection straight into d_out
    oproj_kernel<<<dim3(8, 32), 256>>>(Wo, bo, (float*)d_out);
}